// round 9
// baseline (speedup 1.0000x reference)
#include <cuda_runtime.h>
#include <cuda_bf16.h>

// Problem constants
#define KSZ   9
#define PAD   4
#define H     256
#define W     256
#define HO    248
#define WO    248
#define B     4
#define PLANE (H * W)

// Main path: symmetric half-space over ALL image pairs with uniform factor 2
// (y zeroed only OUTSIDE the image). Offsets: (0,1..4) and (1..4,-4..4) = 40.
// Correction blocks subtract Sum_{p not interior} Sum_{q in image} W*m
// (inclusion-exclusion for the pair weight [p in I] + [q in I]).
#define TW    64
#define TH    8
#define SW    72           // cols tx0-4 .. tx0+67
#define SH    12           // rows ty0 .. ty0+11 (halo below only)
#define NTHR  256

#define GX    4
#define GY    32           // main tiles: full 256 rows; by==GY -> correction
#define NBLK  (GX * (GY + 1) * B)   // 528

#define RING_N 4032        // border-ring positions per batch (8-wide ring)

// -100 * log2(e) : exp(-color/0.01) = 2^(color * NC1)
#define NC1   (-144.26950408889634f)
// log2(e)/9      : dist = 2^(-d2_spatial * DC)
#define DC    (1.4426950408889634f / 9.0f)

typedef unsigned long long ull;

static __device__ float        g_bsums[NBLK];
static __device__ unsigned int g_count = 0;

__device__ __forceinline__ float ex2f(float v) {
    float r;
    asm("ex2.approx.f32 %0, %1;" : "=f"(r) : "f"(v));
    return r;
}
__device__ __forceinline__ ull pk(float lo, float hi) {
    ull r;
    asm("mov.b64 %0, {%1, %2};" : "=l"(r) : "f"(lo), "f"(hi));
    return r;
}
__device__ __forceinline__ void upk(ull v, float& lo, float& hi) {
    asm("mov.b64 {%0, %1}, %2;" : "=f"(lo), "=f"(hi) : "l"(v));
}
__device__ __forceinline__ ull f2add(ull a, ull b) {
    ull r;
    asm("add.rn.f32x2 %0, %1, %2;" : "=l"(r) : "l"(a), "l"(b));
    return r;
}
__device__ __forceinline__ ull f2mul(ull a, ull b) {
    ull r;
    asm("mul.rn.f32x2 %0, %1, %2;" : "=l"(r) : "l"(a), "l"(b));
    return r;
}
__device__ __forceinline__ ull f2fma(ull a, ull b, ull c) {
    ull r;
    asm("fma.rn.f32x2 %0, %1, %2, %3;" : "=l"(r) : "l"(a), "l"(b), "l"(c));
    return r;
}

// Correction for one ring position p=(r,c): Sum over all 80 non-center offsets
// with q in image of W(p,q)*m(p,q). Scalar; reads hit L1.
__device__ float ring_corr(const float* __restrict__ xb,
                           const float* __restrict__ yb, int r, int c) {
    const int po  = r * W + c;
    const float xc0 = xb[po], xc1 = xb[PLANE + po], xc2 = xb[2 * PLANE + po];
    const float y0c = yb[po], y1c = yb[PLANE + po];
    float corr = 0.0f;
    for (int di = -4; di <= 4; di++) {
        const int qr = r + di;
        if ((unsigned)qr > 255u) continue;
        #pragma unroll
        for (int dj = -4; dj <= 4; dj++) {
            if (di == 0 && dj == 0) continue;
            const int qc = c + dj;
            if ((unsigned)qc > 255u) continue;
            const int qo = qr * W + qc;
            float d0 = xc0 - xb[qo];
            float d1 = xc1 - xb[PLANE + qo];
            float d2 = xc2 - xb[2 * PLANE + qo];
            float color = fmaf(d2, d2, fmaf(d1, d1, d0 * d0));
            float c0k = -(float)(di * di + dj * dj) * DC;
            float w = ex2f(fmaf(color, NC1, c0k));
            float m = fmaf(y0c, yb[PLANE + qo], y1c * yb[qo]);
            corr = fmaf(w, m, corr);
        }
    }
    return corr;
}

__global__ __launch_bounds__(NTHR, 3)
void potts_fused(const float* __restrict__ x, const float* __restrict__ y,
                 float* __restrict__ out) {
    __shared__ float s[5][SH][SW];   // x0,x1,x2,y0m,y1m -> 17280 B

    const int b   = blockIdx.z;
    const int tid = threadIdx.x;
    const int lane = tid & 31;
    const float* xb = x + (size_t)b * 3 * PLANE;
    const float* yb = y + (size_t)b * 2 * PLANE;

    float acc;

    if (blockIdx.y == GY) {
        // ---- Correction block: subtract ring contributions ----
        float corr = 0.0f;
        #pragma unroll
        for (int k = 0; k < RING_N / (GX * NTHR) + 1; k++) {
            int pos = blockIdx.x * NTHR + tid + k * GX * NTHR;
            if (pos < RING_N) {
                int r, c;
                if (pos < 1024)       { r = pos >> 8;              c = pos & 255; }
                else if (pos < 2048)  { r = 252 + ((pos - 1024) >> 8); c = pos & 255; }
                else {
                    int rem = pos - 2048;           // 248 rows x 8 side cols
                    r = 4 + (rem >> 3);
                    int cc = rem & 7;
                    c = (cc < 4) ? cc : (248 + cc);
                }
                corr += ring_corr(xb, yb, r, c);
            }
        }
        acc = -corr;   // subtracted from the global sum
    } else {
        // ---- Main tile: half-space, factor 2, full image ----
        const int tx0 = blockIdx.x * TW;
        const int ty0 = blockIdx.y * TH;

        // Halo fill. x: clamped. y: zero OUTSIDE the image only.
        for (int i = tid; i < 5 * SH * SW; i += NTHR) {
            int p  = i / (SH * SW);
            int r  = (i / SW) % SH;
            int c  = i % SW;
            int uy = ty0 + r;
            int ux = tx0 - 4 + c;
            int gy = min(uy, H - 1);
            int gx = min(max(ux, 0), W - 1);
            float v;
            if (p < 3) {
                v = xb[p * PLANE + gy * W + gx];
            } else {
                v = yb[(p - 3) * PLANE + gy * W + gx];
                if ((unsigned)uy > 255u || (unsigned)ux > 255u) v = 0.0f;
            }
            s[p][r][c] = v;
        }
        __syncthreads();

        const int ly  = tid >> 5;     // warp = output row
        const int lx2 = lane * 2;
        const int gr  = ty0 + ly;
        const int gc0 = tx0 + lx2;

        const ull negc0 = pk(-s[0][ly][lx2 + 4], -s[0][ly][lx2 + 5]);
        const ull negc1 = pk(-s[1][ly][lx2 + 4], -s[1][ly][lx2 + 5]);
        const ull negc2 = pk(-s[2][ly][lx2 + 4], -s[2][ly][lx2 + 5]);
        const float y0c0 = s[3][ly][lx2 + 4], y0c1 = s[3][ly][lx2 + 5];
        const float y1c0 = s[4][ly][lx2 + 4], y1c1 = s[4][ly][lx2 + 5];

        ull accA = 0ull;   // Sum_half w * y1_q  (packed col pair)
        ull accB = 0ull;   // Sum_half w * y0_q

        #pragma unroll
        for (int di = 0; di < 5; di++) {
            const int sr = ly + di;
            float v0[10], v1[10], v2[10], q0[10], q1[10];
            const int m0 = (di == 0) ? 2 : 0;
            #pragma unroll
            for (int m = m0; m < 5; m++) {
                float2 t;
                t = *(const float2*)&s[0][sr][lx2 + 2*m]; v0[2*m] = t.x; v0[2*m+1] = t.y;
                t = *(const float2*)&s[1][sr][lx2 + 2*m]; v1[2*m] = t.x; v1[2*m+1] = t.y;
                t = *(const float2*)&s[2][sr][lx2 + 2*m]; v2[2*m] = t.x; v2[2*m+1] = t.y;
                t = *(const float2*)&s[3][sr][lx2 + 2*m]; q0[2*m] = t.x; q0[2*m+1] = t.y;
                t = *(const float2*)&s[4][sr][lx2 + 2*m]; q1[2*m] = t.x; q1[2*m+1] = t.y;
            }
            const int djs = (di == 0) ? 1 : -4;
            #pragma unroll
            for (int dj = djs; dj <= 4; dj++) {
                const int j = dj + 4;
                ull n0 = pk(v0[j], v0[j + 1]);
                ull n1 = pk(v1[j], v1[j + 1]);
                ull n2 = pk(v2[j], v2[j + 1]);
                ull d0 = f2add(n0, negc0);
                ull d1 = f2add(n1, negc1);
                ull d2 = f2add(n2, negc2);
                ull c  = f2mul(d0, d0);
                c = f2fma(d1, d1, c);
                c = f2fma(d2, d2, c);
                float clo, chi;
                upk(c, clo, chi);
                const float c0k = -(float)(di * di + dj * dj) * DC;
                ull wg = pk(ex2f(fmaf(clo, NC1, c0k)), ex2f(fmaf(chi, NC1, c0k)));
                accA = f2fma(wg, pk(q1[j], q1[j + 1]), accA);
                accB = f2fma(wg, pk(q0[j], q0[j + 1]), accB);
            }
        }

        float a0, a1, b0, b1;
        upk(accA, a0, a1);
        upk(accB, b0, b1);
        // Center term keeps the exact weight 2*[p in I].
        const bool f0 = ((unsigned)(gr - 4) <= 247u) && ((unsigned)(gc0 - 4) <= 247u);
        const bool f1 = ((unsigned)(gr - 4) <= 247u) && ((unsigned)(gc0 - 3) <= 247u);
        const float ctr0 = f0 ? y0c0 * y1c0 : 0.0f;
        const float ctr1 = f1 ? y0c1 * y1c1 : 0.0f;
        acc = 2.0f * (fmaf(y0c0, a0, fmaf(y1c0, b0, ctr0)) +
                      fmaf(y0c1, a1, fmaf(y1c1, b1, ctr1)));
    }

    // Deterministic block reduction
    #pragma unroll
    for (int off = 16; off > 0; off >>= 1)
        acc += __shfl_down_sync(0xffffffffu, acc, off);

    __shared__ float wsum[NTHR / 32];
    if (lane == 0) wsum[tid >> 5] = acc;
    __syncthreads();

    __shared__ bool is_last;
    if (tid == 0) {
        float t = 0.0f;
        #pragma unroll
        for (int i = 0; i < NTHR / 32; i++) t += wsum[i];
        const int bid = blockIdx.x + GX * (blockIdx.y + (GY + 1) * blockIdx.z);
        g_bsums[bid] = t;
        __threadfence();
        unsigned int old = atomicAdd(&g_count, 1u);
        is_last = (old == (unsigned)(NBLK - 1));
    }
    __syncthreads();

    if (is_last) {
        __threadfence();
        double dacc = 0.0;
        for (int i = tid; i < NBLK; i += NTHR) dacc += (double)g_bsums[i];
        #pragma unroll
        for (int off = 16; off > 0; off >>= 1)
            dacc += __shfl_down_sync(0xffffffffu, dacc, off);
        __shared__ double dsum[NTHR / 32];
        if (lane == 0) dsum[tid >> 5] = dacc;
        __syncthreads();
        if (tid == 0) {
            double t = 0.0;
            #pragma unroll
            for (int i = 0; i < NTHR / 32; i++) t += dsum[i];
            const double scale = 1.0 / ((double)B * 81.0 * (double)HO * (double)WO);
            out[0] = (float)(t * scale);
            g_count = 0;   // reset for next graph replay
        }
    }
}

extern "C" void kernel_launch(void* const* d_in, const int* in_sizes, int n_in,
                              void* d_out, int out_size) {
    const float* x = (const float*)d_in[0];   // [4,3,256,256]
    const float* y = (const float*)d_in[1];   // [4,2,256,256]
    float* out = (float*)d_out;

    // Bias L1/shared split toward shared so 3 blocks (51.8 KB) can be resident.
    cudaFuncSetAttribute(potts_fused,
                         cudaFuncAttributePreferredSharedMemoryCarveout,
                         cudaSharedmemCarveoutMaxShared);

    dim3 grid(GX, GY + 1, B);
    potts_fused<<<grid, NTHR>>>(x, y, out);
}

// round 10
// speedup vs baseline: 1.1374x; 1.1374x over previous
#include <cuda_runtime.h>
#include <cuda_bf16.h>

// Problem constants
#define KSZ   9
#define PAD   4
#define H     256
#define W     256
#define HO    248
#define WO    248
#define B     4
#define PLANE (H * W)

// Main path: symmetric half-space over ALL image pairs, uniform factor 2
// (y zeroed only OUTSIDE the image). Offsets: (0,1..4) and (1..4,-4..4) = 40.
// Correction blocks subtract Sum_{p not interior} Sum_{q in image} W*m
// (inclusion-exclusion for the pair weight [p in I] + [q in I]).
#define TW    64
#define TH    8
#define SW    72           // cols tx0-4 .. tx0+67
#define SH    12           // rows ty0 .. ty0+11 (halo below only)
#define NTHR  256

#define GX    4
#define CORR_BY 4          // grid-y rows 0..3 = correction (launched first)
#define GY    32           // main tiles: grid-y rows 4..35
#define GYT   (CORR_BY + GY)
#define NBLK  (GX * GYT * B)   // 576

#define RING_N 4032        // border-ring positions per batch (8-wide ring)

// -100 * log2(e) : exp(-color/0.01) = 2^(color * NC1)
#define NC1   (-144.26950408889634f)
// log2(e)/9      : dist = 2^(-d2_spatial * DC)
#define DC    (1.4426950408889634f / 9.0f)

typedef unsigned long long ull;

static __device__ float        g_bsums[NBLK];
static __device__ unsigned int g_count = 0;

__device__ __forceinline__ float ex2f(float v) {
    float r;
    asm("ex2.approx.f32 %0, %1;" : "=f"(r) : "f"(v));
    return r;
}
__device__ __forceinline__ ull pk(float lo, float hi) {
    ull r;
    asm("mov.b64 %0, {%1, %2};" : "=l"(r) : "f"(lo), "f"(hi));
    return r;
}
__device__ __forceinline__ void upk(ull v, float& lo, float& hi) {
    asm("mov.b64 {%0, %1}, %2;" : "=f"(lo), "=f"(hi) : "l"(v));
}
__device__ __forceinline__ ull f2add(ull a, ull b) {
    ull r;
    asm("add.rn.f32x2 %0, %1, %2;" : "=l"(r) : "l"(a), "l"(b));
    return r;
}
__device__ __forceinline__ ull f2mul(ull a, ull b) {
    ull r;
    asm("mul.rn.f32x2 %0, %1, %2;" : "=l"(r) : "l"(a), "l"(b));
    return r;
}
__device__ __forceinline__ ull f2fma(ull a, ull b, ull c) {
    ull r;
    asm("fma.rn.f32x2 %0, %1, %2, %3;" : "=l"(r) : "l"(a), "l"(b), "l"(c));
    return r;
}

// Correction for one ring position p=(r,c): Sum over all non-center offsets
// with q in image of W(p,q)*m(p,q). Clamped addresses + zero flags (no
// branches) so the 45 loads of each di-row issue back-to-back (high MLP).
__device__ float ring_corr(const float* __restrict__ xb,
                           const float* __restrict__ yb, int r, int c) {
    const int po  = r * W + c;
    const float xc0 = xb[po], xc1 = xb[PLANE + po], xc2 = xb[2 * PLANE + po];
    const float y0c = yb[po], y1c = yb[PLANE + po];
    float corr = 0.0f;
    #pragma unroll
    for (int di = -4; di <= 4; di++) {
        const int qr_raw = r + di;
        const bool rowOK = (unsigned)qr_raw <= 255u;
        const int qr = min(max(qr_raw, 0), H - 1);
        const int base = qr * W;
        #pragma unroll
        for (int dj = -4; dj <= 4; dj++) {
            const int qc_raw = c + dj;
            const bool ok = rowOK && ((unsigned)qc_raw <= 255u) &&
                            !(di == 0 && dj == 0);
            const int qc = min(max(qc_raw, 0), W - 1);
            const int qo = base + qc;
            float d0 = xc0 - xb[qo];
            float d1 = xc1 - xb[PLANE + qo];
            float d2 = xc2 - xb[2 * PLANE + qo];
            float color = fmaf(d2, d2, fmaf(d1, d1, d0 * d0));
            float c0k = -(float)(di * di + dj * dj) * DC;
            float w = ex2f(fmaf(color, NC1, c0k));
            float m = fmaf(y0c, yb[PLANE + qo], y1c * yb[qo]);
            corr = fmaf(ok ? w : 0.0f, m, corr);
        }
    }
    return corr;
}

__global__ __launch_bounds__(NTHR, 3)
void potts_fused(const float* __restrict__ x, const float* __restrict__ y,
                 float* __restrict__ out) {
    __shared__ float s[5][SH][SW];   // x0,x1,x2,y0m,y1m -> 17280 B

    const int b    = blockIdx.z;
    const int tid  = threadIdx.x;
    const int lane = tid & 31;
    const float* xb = x + (size_t)b * 3 * PLANE;
    const float* yb = y + (size_t)b * 2 * PLANE;

    float acc;

    if (blockIdx.y < CORR_BY) {
        // ---- Correction: one ring position per thread ----
        const int pos = (blockIdx.y * GX + blockIdx.x) * NTHR + tid;
        float corr = 0.0f;
        if (pos < RING_N) {
            int r, c;
            if (pos < 1024)      { r = pos >> 8;                 c = pos & 255; }
            else if (pos < 2048) { r = 252 + ((pos - 1024) >> 8); c = pos & 255; }
            else {
                int rem = pos - 2048;            // 248 rows x 8 side cols
                r = 4 + (rem >> 3);
                int cc = rem & 7;
                c = (cc < 4) ? cc : (248 + cc);
            }
            corr = ring_corr(xb, yb, r, c);
        }
        acc = -corr;   // subtracted from the global sum
    } else {
        // ---- Main tile: half-space, factor 2, full image ----
        const int tx0 = blockIdx.x * TW;
        const int ty0 = (blockIdx.y - CORR_BY) * TH;

        // Halo fill. x: clamped. y: zero OUTSIDE the image only.
        for (int i = tid; i < 5 * SH * SW; i += NTHR) {
            int p  = i / (SH * SW);
            int r  = (i / SW) % SH;
            int c  = i % SW;
            int uy = ty0 + r;
            int ux = tx0 - 4 + c;
            int gy = min(uy, H - 1);
            int gx = min(max(ux, 0), W - 1);
            float v;
            if (p < 3) {
                v = xb[p * PLANE + gy * W + gx];
            } else {
                v = yb[(p - 3) * PLANE + gy * W + gx];
                if ((unsigned)uy > 255u || (unsigned)ux > 255u) v = 0.0f;
            }
            s[p][r][c] = v;
        }
        __syncthreads();

        const int ly  = tid >> 5;     // warp = output row
        const int lx2 = lane * 2;
        const int gr  = ty0 + ly;
        const int gc0 = tx0 + lx2;

        const ull negc0 = pk(-s[0][ly][lx2 + 4], -s[0][ly][lx2 + 5]);
        const ull negc1 = pk(-s[1][ly][lx2 + 4], -s[1][ly][lx2 + 5]);
        const ull negc2 = pk(-s[2][ly][lx2 + 4], -s[2][ly][lx2 + 5]);
        const float y0c0 = s[3][ly][lx2 + 4], y0c1 = s[3][ly][lx2 + 5];
        const float y1c0 = s[4][ly][lx2 + 4], y1c1 = s[4][ly][lx2 + 5];

        ull accA = 0ull;   // Sum_half w * y1_q  (packed col pair)
        ull accB = 0ull;   // Sum_half w * y0_q

        #pragma unroll
        for (int di = 0; di < 5; di++) {
            const int sr = ly + di;
            float v0[10], v1[10], v2[10], q0[10], q1[10];
            const int m0 = (di == 0) ? 2 : 0;
            #pragma unroll
            for (int m = m0; m < 5; m++) {
                float2 t;
                t = *(const float2*)&s[0][sr][lx2 + 2*m]; v0[2*m] = t.x; v0[2*m+1] = t.y;
                t = *(const float2*)&s[1][sr][lx2 + 2*m]; v1[2*m] = t.x; v1[2*m+1] = t.y;
                t = *(const float2*)&s[2][sr][lx2 + 2*m]; v2[2*m] = t.x; v2[2*m+1] = t.y;
                t = *(const float2*)&s[3][sr][lx2 + 2*m]; q0[2*m] = t.x; q0[2*m+1] = t.y;
                t = *(const float2*)&s[4][sr][lx2 + 2*m]; q1[2*m] = t.x; q1[2*m+1] = t.y;
            }
            const int djs = (di == 0) ? 1 : -4;
            #pragma unroll
            for (int dj = djs; dj <= 4; dj++) {
                const int j = dj + 4;
                ull n0 = pk(v0[j], v0[j + 1]);
                ull n1 = pk(v1[j], v1[j + 1]);
                ull n2 = pk(v2[j], v2[j + 1]);
                ull d0 = f2add(n0, negc0);
                ull d1 = f2add(n1, negc1);
                ull d2 = f2add(n2, negc2);
                ull c  = f2mul(d0, d0);
                c = f2fma(d1, d1, c);
                c = f2fma(d2, d2, c);
                float clo, chi;
                upk(c, clo, chi);
                const float c0k = -(float)(di * di + dj * dj) * DC;
                ull wg = pk(ex2f(fmaf(clo, NC1, c0k)), ex2f(fmaf(chi, NC1, c0k)));
                accA = f2fma(wg, pk(q1[j], q1[j + 1]), accA);
                accB = f2fma(wg, pk(q0[j], q0[j + 1]), accB);
            }
        }

        float a0, a1, b0, b1;
        upk(accA, a0, a1);
        upk(accB, b0, b1);
        // Center term keeps the exact weight 2*[p in I].
        const bool f0 = ((unsigned)(gr - 4) <= 247u) && ((unsigned)(gc0 - 4) <= 247u);
        const bool f1 = ((unsigned)(gr - 4) <= 247u) && ((unsigned)(gc0 - 3) <= 247u);
        const float ctr0 = f0 ? y0c0 * y1c0 : 0.0f;
        const float ctr1 = f1 ? y0c1 * y1c1 : 0.0f;
        acc = 2.0f * (fmaf(y0c0, a0, fmaf(y1c0, b0, ctr0)) +
                      fmaf(y0c1, a1, fmaf(y1c1, b1, ctr1)));
    }

    // Deterministic block reduction
    #pragma unroll
    for (int off = 16; off > 0; off >>= 1)
        acc += __shfl_down_sync(0xffffffffu, acc, off);

    __shared__ float wsum[NTHR / 32];
    if (lane == 0) wsum[tid >> 5] = acc;
    __syncthreads();

    __shared__ bool is_last;
    if (tid == 0) {
        float t = 0.0f;
        #pragma unroll
        for (int i = 0; i < NTHR / 32; i++) t += wsum[i];
        const int bid = blockIdx.x + GX * (blockIdx.y + GYT * blockIdx.z);
        g_bsums[bid] = t;
        __threadfence();
        unsigned int old = atomicAdd(&g_count, 1u);
        is_last = (old == (unsigned)(NBLK - 1));
    }
    __syncthreads();

    if (is_last) {
        __threadfence();
        double dacc = 0.0;
        for (int i = tid; i < NBLK; i += NTHR) dacc += (double)g_bsums[i];
        #pragma unroll
        for (int off = 16; off > 0; off >>= 1)
            dacc += __shfl_down_sync(0xffffffffu, dacc, off);
        __shared__ double dsum[NTHR / 32];
        if (lane == 0) dsum[tid >> 5] = dacc;
        __syncthreads();
        if (tid == 0) {
            double t = 0.0;
            #pragma unroll
            for (int i = 0; i < NTHR / 32; i++) t += dsum[i];
            const double scale = 1.0 / ((double)B * 81.0 * (double)HO * (double)WO);
            out[0] = (float)(t * scale);
            g_count = 0;   // reset for next graph replay
        }
    }
}

extern "C" void kernel_launch(void* const* d_in, const int* in_sizes, int n_in,
                              void* d_out, int out_size) {
    const float* x = (const float*)d_in[0];   // [4,3,256,256]
    const float* y = (const float*)d_in[1];   // [4,2,256,256]
    float* out = (float*)d_out;

    // Bias L1/shared split toward shared so 3 blocks (51.8 KB) can be resident.
    cudaFuncSetAttribute(potts_fused,
                         cudaFuncAttributePreferredSharedMemoryCarveout,
                         cudaSharedmemCarveoutMaxShared);

    dim3 grid(GX, GYT, B);
    potts_fused<<<grid, NTHR>>>(x, y, out);
}

// round 11
// speedup vs baseline: 3.1039x; 2.7289x over previous
#include <cuda_runtime.h>
#include <cuda_bf16.h>

// Problem constants
#define KSZ   9
#define PAD   4
#define H     256
#define W     256
#define HO    248
#define WO    248
#define B     4
#define PLANE (H * W)

// Half-space pair enumeration over the full image, pair weight fp+fq carried
// algebraically: term1 (unmasked q, fp in epilogue) + term2 (fq-masked q).
// Offsets: di=0,dj=1..4 and di=1..4,dj=-4..4  -> 40 taps. Center handled in
// the epilogue with weight 2*fp.
#define TW    64
#define TH    8
#define SW    72           // cols tx0-4 .. tx0+67
#define SH    12           // rows ty0 .. ty0+11 (halo below only)
#define NTHR  256

#define GX    4
#define GY    32           // full 256 image rows
#define NBLK  (GX * GY * B)   // 512

// -100 * log2(e) : exp(-color/0.01) = 2^(color * NC1)
#define NC1   (-144.26950408889634f)
// log2(e)/9      : dist = 2^(-d2_spatial * DC)
#define DC    (1.4426950408889634f / 9.0f)

typedef unsigned long long ull;

static __device__ float        g_bsums[NBLK];
static __device__ unsigned int g_count = 0;

__device__ __forceinline__ float ex2f(float v) {
    float r;
    asm("ex2.approx.f32 %0, %1;" : "=f"(r) : "f"(v));
    return r;
}
__device__ __forceinline__ ull pk(float lo, float hi) {
    ull r;
    asm("mov.b64 %0, {%1, %2};" : "=l"(r) : "f"(lo), "f"(hi));
    return r;
}
__device__ __forceinline__ void upk(ull v, float& lo, float& hi) {
    asm("mov.b64 {%0, %1}, %2;" : "=f"(lo), "=f"(hi) : "l"(v));
}
__device__ __forceinline__ ull f2add(ull a, ull b) {
    ull r;
    asm("add.rn.f32x2 %0, %1, %2;" : "=l"(r) : "l"(a), "l"(b));
    return r;
}
__device__ __forceinline__ ull f2mul(ull a, ull b) {
    ull r;
    asm("mul.rn.f32x2 %0, %1, %2;" : "=l"(r) : "l"(a), "l"(b));
    return r;
}
__device__ __forceinline__ ull f2fma(ull a, ull b, ull c) {
    ull r;
    asm("fma.rn.f32x2 %0, %1, %2, %3;" : "=l"(r) : "l"(a), "l"(b), "l"(c));
    return r;
}

__global__ __launch_bounds__(NTHR, 2)
void potts_fused(const float* __restrict__ x, const float* __restrict__ y,
                 float* __restrict__ out) {
    __shared__ float s[5][SH][SW];   // x0,x1,x2,y0,y1 -> 17280 B

    const int b   = blockIdx.z;
    const int tx0 = blockIdx.x * TW;
    const int ty0 = blockIdx.y * TH;
    const int tid = threadIdx.x;

    const float* xb = x + (size_t)b * 3 * PLANE;
    const float* yb = y + (size_t)b * 2 * PLANE;

    // Halo fill. x: clamped. y: zeroed OUTSIDE the image (pairs reaching
    // off-image q contribute 0; in-image y stays real for term1).
    for (int i = tid; i < 5 * SH * SW; i += NTHR) {
        int p  = i / (SH * SW);
        int r  = (i / SW) % SH;
        int c  = i % SW;
        int uy = ty0 + r;
        int ux = tx0 - 4 + c;
        int gy = min(uy, H - 1);
        int gx = min(max(ux, 0), W - 1);
        float v;
        if (p < 3) {
            v = xb[p * PLANE + gy * W + gx];
        } else {
            v = yb[(p - 3) * PLANE + gy * W + gx];
            if ((unsigned)uy > 255u || (unsigned)ux > 255u) v = 0.0f;
        }
        s[p][r][c] = v;
    }
    __syncthreads();

    const int lane = tid & 31;
    const int ly   = tid >> 5;          // warp = output row
    const int lx2  = lane * 2;
    const int gr   = ty0 + ly;          // global p row
    const int gc0  = tx0 + lx2;         // global p col (of packed lo)

    // Packed negated x centers
    const ull negc0 = pk(-s[0][ly][lx2 + 4], -s[0][ly][lx2 + 5]);
    const ull negc1 = pk(-s[1][ly][lx2 + 4], -s[1][ly][lx2 + 5]);
    const ull negc2 = pk(-s[2][ly][lx2 + 4], -s[2][ly][lx2 + 5]);
    const float y0c0 = s[3][ly][lx2 + 4], y0c1 = s[3][ly][lx2 + 5];
    const float y1c0 = s[4][ly][lx2 + 4], y1c1 = s[4][ly][lx2 + 5];

    // Precomputed packed column-interior masks for q: col gc0+dj (dj=j-4).
    ull mj[9];
    #pragma unroll
    for (int j = 0; j < 9; j++) {
        const int cq = gc0 + j - 4;
        const float f0 = ((unsigned)(cq - 4) <= 247u) ? 1.0f : 0.0f;
        const float f1 = ((unsigned)(cq - 3) <= 247u) ? 1.0f : 0.0f;
        mj[j] = pk(f0, f1);
    }

    ull accA = 0ull;   // term1: Sum w * y1_q       (packed col pair)
    ull accB = 0ull;   // term1: Sum w * y0_q
    ull accC = 0ull;   // term2: Sum w * y1_q * fq
    ull accD = 0ull;   // term2: Sum w * y0_q * fq

    #pragma unroll
    for (int di = 0; di < 5; di++) {
        const int sr = ly + di;
        // Full 10-wide windows per plane (aligned float2; fully initialized)
        float v0[10], v1[10], v2[10], q0[10], q1[10];
        #pragma unroll
        for (int m = 0; m < 5; m++) {
            float2 t;
            t = *(const float2*)&s[0][sr][lx2 + 2*m]; v0[2*m] = t.x; v0[2*m+1] = t.y;
            t = *(const float2*)&s[1][sr][lx2 + 2*m]; v1[2*m] = t.x; v1[2*m+1] = t.y;
            t = *(const float2*)&s[2][sr][lx2 + 2*m]; v2[2*m] = t.x; v2[2*m+1] = t.y;
            t = *(const float2*)&s[3][sr][lx2 + 2*m]; q0[2*m] = t.x; q0[2*m+1] = t.y;
            t = *(const float2*)&s[4][sr][lx2 + 2*m]; q1[2*m] = t.x; q1[2*m+1] = t.y;
        }
        // q-row interior mask, uniform within this di (AND-mask on mj)
        const ull mrow = ((unsigned)(gr + di - 4) <= 247u) ? ~0ull : 0ull;
        #pragma unroll
        for (int dj = -4; dj <= 4; dj++) {
            if (di == 0 && dj <= 0) continue;   // compile-time half-space skip
            const int j = dj + 4;
            ull n0 = pk(v0[j], v0[j + 1]);
            ull n1 = pk(v1[j], v1[j + 1]);
            ull n2 = pk(v2[j], v2[j + 1]);
            ull d0 = f2add(n0, negc0);
            ull d1 = f2add(n1, negc1);
            ull d2 = f2add(n2, negc2);
            ull c  = f2mul(d0, d0);
            c = f2fma(d1, d1, c);
            c = f2fma(d2, d2, c);
            float clo, chi;
            upk(c, clo, chi);
            const float c0k = -(float)(di * di + dj * dj) * DC;
            ull w = pk(ex2f(fmaf(clo, NC1, c0k)), ex2f(fmaf(chi, NC1, c0k)));
            ull ny1 = pk(q1[j], q1[j + 1]);
            ull ny0 = pk(q0[j], q0[j + 1]);
            accA = f2fma(w, ny1, accA);
            accB = f2fma(w, ny0, accB);
            const ull mq = mj[j] & mrow;        // fq packed {0,1}
            accC = f2fma(w, f2mul(ny1, mq), accC);
            accD = f2fma(w, f2mul(ny0, mq), accD);
        }
    }

    float a0, a1, b0, b1, c0v, c1v, d0v, d1v;
    upk(accA, a0, a1);
    upk(accB, b0, b1);
    upk(accC, c0v, c1v);
    upk(accD, d0v, d1v);

    // fp per packed column
    const bool rI = (unsigned)(gr - 4) <= 247u;
    const float fp0 = (rI && (unsigned)(gc0 - 4) <= 247u) ? 1.0f : 0.0f;
    const float fp1 = (rI && (unsigned)(gc0 - 3) <= 247u) ? 1.0f : 0.0f;

    // col: fp*(y0c*A + y1c*B + 2*y0c*y1c) + (y0c*C + y1c*D)
    const float t0 = fmaf(y0c0, a0, fmaf(y1c0, b0, 2.0f * y0c0 * y1c0));
    const float t1 = fmaf(y0c1, a1, fmaf(y1c1, b1, 2.0f * y0c1 * y1c1));
    const float u0 = fmaf(y0c0, c0v, y1c0 * d0v);
    const float u1 = fmaf(y0c1, c1v, y1c1 * d1v);
    float acc = fmaf(fp0, t0, u0) + fmaf(fp1, t1, u1);

    // Deterministic block reduction
    #pragma unroll
    for (int off = 16; off > 0; off >>= 1)
        acc += __shfl_down_sync(0xffffffffu, acc, off);

    __shared__ float wsum[NTHR / 32];
    if (lane == 0) wsum[ly] = acc;
    __syncthreads();

    __shared__ bool is_last;
    if (tid == 0) {
        float t = 0.0f;
        #pragma unroll
        for (int i = 0; i < NTHR / 32; i++) t += wsum[i];
        const int bid = blockIdx.x + GX * (blockIdx.y + GY * blockIdx.z);
        g_bsums[bid] = t;
        __threadfence();
        unsigned int old = atomicAdd(&g_count, 1u);
        is_last = (old == (unsigned)(NBLK - 1));
    }
    __syncthreads();

    if (is_last) {
        __threadfence();
        double dacc = 0.0;
        for (int i = tid; i < NBLK; i += NTHR) dacc += (double)g_bsums[i];
        #pragma unroll
        for (int off = 16; off > 0; off >>= 1)
            dacc += __shfl_down_sync(0xffffffffu, dacc, off);
        __shared__ double dsum[NTHR / 32];
        if (lane == 0) dsum[tid >> 5] = dacc;
        __syncthreads();
        if (tid == 0) {
            double t = 0.0;
            #pragma unroll
            for (int i = 0; i < NTHR / 32; i++) t += dsum[i];
            const double scale = 1.0 / ((double)B * 81.0 * (double)HO * (double)WO);
            out[0] = (float)(t * scale);
            g_count = 0;   // reset for next graph replay
        }
    }
}

extern "C" void kernel_launch(void* const* d_in, const int* in_sizes, int n_in,
                              void* d_out, int out_size) {
    const float* x = (const float*)d_in[0];   // [4,3,256,256]
    const float* y = (const float*)d_in[1];   // [4,2,256,256]
    float* out = (float*)d_out;

    dim3 grid(GX, GY, B);
    potts_fused<<<grid, NTHR>>>(x, y, out);
}

// round 13
// speedup vs baseline: 3.3233x; 1.0707x over previous
#include <cuda_runtime.h>
#include <cuda_bf16.h>

// Problem constants
#define KSZ   9
#define PAD   4
#define H     256
#define W     256
#define HO    248
#define WO    248
#define B     4
#define PLANE (H * W)

// Half-space pair enumeration over the full image; each unordered pair gets
// weight (fp + fq) folded into the exp weight: wt = w * (fp + fq).
// Offsets: di=0,dj=1..4 and di=1..4,dj=-4..4 -> 40 taps. Center: 2*fp*y0*y1.
#define TW    64
#define TH    8
#define SW    72           // cols tx0-4 .. tx0+67
#define SH    12           // rows ty0 .. ty0+11 (halo below only)
#define NTHR  256

#define GX    4
#define GY    32           // full 256 image rows
#define NBLK  (GX * GY * B)   // 512

// -100 * log2(e) : exp(-color/0.01) = 2^(color * NC1)
#define NC1   (-144.26950408889634f)
// log2(e)/9      : dist = 2^(-d2_spatial * DC)
#define DC    (1.4426950408889634f / 9.0f)

typedef unsigned long long ull;

static __device__ float        g_bsums[NBLK];
static __device__ unsigned int g_count = 0;

__device__ __forceinline__ float ex2f(float v) {
    float r;
    asm("ex2.approx.f32 %0, %1;" : "=f"(r) : "f"(v));
    return r;
}
__device__ __forceinline__ ull pk(float lo, float hi) {
    ull r;
    asm("mov.b64 %0, {%1, %2};" : "=l"(r) : "f"(lo), "f"(hi));
    return r;
}
__device__ __forceinline__ void upk(ull v, float& lo, float& hi) {
    asm("mov.b64 {%0, %1}, %2;" : "=f"(lo), "=f"(hi) : "l"(v));
}
// {hi(a), lo(b)} -- the odd-offset packed pair from two adjacent aligned pairs
__device__ __forceinline__ ull comb(ull a, ull b) {
    ull r;
    asm("{\n\t"
        ".reg .b32 al, ah, bl, bh;\n\t"
        "mov.b64 {al, ah}, %1;\n\t"
        "mov.b64 {bl, bh}, %2;\n\t"
        "mov.b64 %0, {ah, bl};\n\t"
        "}" : "=l"(r) : "l"(a), "l"(b));
    return r;
}
__device__ __forceinline__ ull f2add(ull a, ull b) {
    ull r;
    asm("add.rn.f32x2 %0, %1, %2;" : "=l"(r) : "l"(a), "l"(b));
    return r;
}
__device__ __forceinline__ ull f2mul(ull a, ull b) {
    ull r;
    asm("mul.rn.f32x2 %0, %1, %2;" : "=l"(r) : "l"(a), "l"(b));
    return r;
}
__device__ __forceinline__ ull f2fma(ull a, ull b, ull c) {
    ull r;
    asm("fma.rn.f32x2 %0, %1, %2, %3;" : "=l"(r) : "l"(a), "l"(b), "l"(c));
    return r;
}

__global__ __launch_bounds__(NTHR, 2)
void potts_fused(const float* __restrict__ x, const float* __restrict__ y,
                 float* __restrict__ out) {
    __shared__ float s[5][SH][SW];   // x0,x1,x2,y0,y1 -> 17280 B

    const int b   = blockIdx.z;
    const int tx0 = blockIdx.x * TW;
    const int ty0 = blockIdx.y * TH;
    const int tid = threadIdx.x;

    const float* xb = x + (size_t)b * 3 * PLANE;
    const float* yb = y + (size_t)b * 2 * PLANE;

    // Halo fill. x: clamped. y: zeroed OUTSIDE the image.
    for (int i = tid; i < 5 * SH * SW; i += NTHR) {
        int p  = i / (SH * SW);
        int r  = (i / SW) % SH;
        int c  = i % SW;
        int uy = ty0 + r;
        int ux = tx0 - 4 + c;
        int gy = min(uy, H - 1);
        int gx = min(max(ux, 0), W - 1);
        float v;
        if (p < 3) {
            v = xb[p * PLANE + gy * W + gx];
        } else {
            v = yb[(p - 3) * PLANE + gy * W + gx];
            if ((unsigned)uy > 255u || (unsigned)ux > 255u) v = 0.0f;
        }
        s[p][r][c] = v;
    }
    __syncthreads();

    const int lane = tid & 31;
    const int ly   = tid >> 5;          // warp = output row
    const int lx2  = lane * 2;
    const int gr   = ty0 + ly;          // global p row
    const int gc0  = tx0 + lx2;         // global p col (packed lo)

    // Packed negated x centers
    const ull negc0 = pk(-s[0][ly][lx2 + 4], -s[0][ly][lx2 + 5]);
    const ull negc1 = pk(-s[1][ly][lx2 + 4], -s[1][ly][lx2 + 5]);
    const ull negc2 = pk(-s[2][ly][lx2 + 4], -s[2][ly][lx2 + 5]);
    const float y0c0 = s[3][ly][lx2 + 4], y0c1 = s[3][ly][lx2 + 5];
    const float y1c0 = s[4][ly][lx2 + 4], y1c1 = s[4][ly][lx2 + 5];

    // fp per packed column (thread constant)
    const bool rI = (unsigned)(gr - 4) <= 247u;
    const float fp0 = (rI && (unsigned)(gc0 - 4) <= 247u) ? 1.0f : 0.0f;
    const float fp1 = (rI && (unsigned)(gc0 - 3) <= 247u) ? 1.0f : 0.0f;
    const ull fp_pk = pk(fp0, fp1);

    // Packed column-interior masks for q at col gc0+dj (bits of 1.0f / 0.0f)
    ull mj[9];
    #pragma unroll
    for (int j = 0; j < 9; j++) {
        const int cq = gc0 + j - 4;
        const float f0 = ((unsigned)(cq - 4) <= 247u) ? 1.0f : 0.0f;
        const float f1 = ((unsigned)(cq - 3) <= 247u) ? 1.0f : 0.0f;
        mj[j] = pk(f0, f1);
    }

    ull accA = 0ull;   // Sum wt * y1_q  (packed col pair), wt = w*(fp+fq)
    ull accB = 0ull;   // Sum wt * y0_q

    #pragma unroll
    for (int di = 0; di < 5; di++) {
        const int sr = ly + di;
        // 5 aligned packed pairs per plane = the 10-wide window
        ull U0[5], U1[5], U2[5], Q0[5], Q1[5];
        #pragma unroll
        for (int m = 0; m < 5; m++) {
            U0[m] = *(const ull*)&s[0][sr][lx2 + 2 * m];
            U1[m] = *(const ull*)&s[1][sr][lx2 + 2 * m];
            U2[m] = *(const ull*)&s[2][sr][lx2 + 2 * m];
            Q0[m] = *(const ull*)&s[3][sr][lx2 + 2 * m];
            Q1[m] = *(const ull*)&s[4][sr][lx2 + 2 * m];
        }
        // q-row interior mask, uniform within this di
        const ull mrow = ((unsigned)(gr + di - 4) <= 247u) ? ~0ull : 0ull;
        const float didi_dc = (float)(di * di) * DC;

        // One tap at window index J_ (= dj+4). Even J_: the aligned packed
        // pair is used directly (no MOVs). Odd J_: one comb (2 MOVs).
        #define ONE_TAP(J_, DJ_)                                            \
        {                                                                   \
            ull d0 = f2add((((J_) & 1) == 0 ? U0[(J_)/2]                    \
                           : comb(U0[((J_)-1)/2], U0[((J_)+1)/2])), negc0); \
            ull d1 = f2add((((J_) & 1) == 0 ? U1[(J_)/2]                    \
                           : comb(U1[((J_)-1)/2], U1[((J_)+1)/2])), negc1); \
            ull d2 = f2add((((J_) & 1) == 0 ? U2[(J_)/2]                    \
                           : comb(U2[((J_)-1)/2], U2[((J_)+1)/2])), negc2); \
            ull cc = f2mul(d0, d0);                                         \
            cc = f2fma(d1, d1, cc);                                         \
            cc = f2fma(d2, d2, cc);                                         \
            float clo, chi;                                                 \
            upk(cc, clo, chi);                                              \
            const float ck = -(float)((DJ_) * (DJ_)) * DC - didi_dc;        \
            ull w  = pk(ex2f(fmaf(clo, NC1, ck)),                           \
                        ex2f(fmaf(chi, NC1, ck)));                          \
            ull mq = mj[(J_)] & mrow;                                       \
            ull wt = f2mul(w, f2add(mq, fp_pk));                            \
            accA = f2fma(wt, (((J_) & 1) == 0 ? Q1[(J_)/2]                  \
                         : comb(Q1[((J_)-1)/2], Q1[((J_)+1)/2])), accA);    \
            accB = f2fma(wt, (((J_) & 1) == 0 ? Q0[(J_)/2]                  \
                         : comb(Q0[((J_)-1)/2], Q0[((J_)+1)/2])), accB);    \
        }

        if (di != 0) {
            ONE_TAP(0, -4) ONE_TAP(1, -3) ONE_TAP(2, -2) ONE_TAP(3, -1)
            ONE_TAP(4,  0)
        }
        ONE_TAP(5, 1) ONE_TAP(6, 2) ONE_TAP(7, 3) ONE_TAP(8, 4)
        #undef ONE_TAP
    }

    float a0, a1, b0, b1;
    upk(accA, a0, a1);
    upk(accB, b0, b1);

    // col: y0c*A + y1c*B + 2*fp*y0c*y1c
    float acc = fmaf(y0c0, a0, fmaf(y1c0, b0, 2.0f * fp0 * y0c0 * y1c0)) +
                fmaf(y0c1, a1, fmaf(y1c1, b1, 2.0f * fp1 * y0c1 * y1c1));

    // Deterministic block reduction
    #pragma unroll
    for (int off = 16; off > 0; off >>= 1)
        acc += __shfl_down_sync(0xffffffffu, acc, off);

    __shared__ float wsum[NTHR / 32];
    if (lane == 0) wsum[ly] = acc;
    __syncthreads();

    __shared__ bool is_last;
    if (tid == 0) {
        float t = 0.0f;
        #pragma unroll
        for (int i = 0; i < NTHR / 32; i++) t += wsum[i];
        const int bid = blockIdx.x + GX * (blockIdx.y + GY * blockIdx.z);
        g_bsums[bid] = t;
        __threadfence();
        unsigned int old = atomicAdd(&g_count, 1u);
        is_last = (old == (unsigned)(NBLK - 1));
    }
    __syncthreads();

    if (is_last) {
        __threadfence();
        double dacc = 0.0;
        for (int i = tid; i < NBLK; i += NTHR) dacc += (double)g_bsums[i];
        #pragma unroll
        for (int off = 16; off > 0; off >>= 1)
            dacc += __shfl_down_sync(0xffffffffu, dacc, off);
        __shared__ double dsum[NTHR / 32];
        if (lane == 0) dsum[tid >> 5] = dacc;
        __syncthreads();
        if (tid == 0) {
            double t = 0.0;
            #pragma unroll
            for (int i = 0; i < NTHR / 32; i++) t += dsum[i];
            const double scale = 1.0 / ((double)B * 81.0 * (double)HO * (double)WO);
            out[0] = (float)(t * scale);
            g_count = 0;   // reset for next graph replay
        }
    }
}

extern "C" void kernel_launch(void* const* d_in, const int* in_sizes, int n_in,
                              void* d_out, int out_size) {
    const float* x = (const float*)d_in[0];   // [4,3,256,256]
    const float* y = (const float*)d_in[1];   // [4,2,256,256]
    float* out = (float*)d_out;

    dim3 grid(GX, GY, B);
    potts_fused<<<grid, NTHR>>>(x, y, out);
}